// round 9
// baseline (speedup 1.0000x reference)
#include <cuda_runtime.h>
#include <cuda_fp16.h>
#include <cuda_bf16.h>
#include <cstdint>

#define OUT_F 11008
#define IN_F  4096
#define NGROW 32            // groups per output row (4096/128)
#define LUT_N (352256 * 16)
#define TPB   576
#define WPB   18            // warps per block

// Permuted transposed x: slot = (g*4 + j)*32 + lane holds column c = g*128 + 4*lane + j
__device__ float4 g_xa[IN_F];   // batches 0-3
__device__ float4 g_xb[IN_F];   // batches 4-7

__global__ void transpose_x_kernel(const float* __restrict__ x) {
    int c = blockIdx.x * blockDim.x + threadIdx.x;
    if (c < IN_F) {
        int g = c >> 7, w = c & 127, l = w >> 2, j = w & 3;
        int slot = (g * 4 + j) * 32 + l;
        float4 a, b;
        a.x = x[0 * IN_F + c]; a.y = x[1 * IN_F + c];
        a.z = x[2 * IN_F + c]; a.w = x[3 * IN_F + c];
        b.x = x[4 * IN_F + c]; b.y = x[5 * IN_F + c];
        b.z = x[6 * IN_F + c]; b.w = x[7 * IN_F + c];
        g_xa[slot] = a; g_xb[slot] = b;
    }
}

__device__ __forceinline__ bool plaus(float v) {
    float a = fabsf(v);
    return isfinite(v) && a > 1e-4f && a < 0.25f;
}

__device__ __forceinline__ float cvtE(__half v)        { return __half2float(v); }
__device__ __forceinline__ float cvtE(__nv_bfloat16 v) { return __bfloat162float(v); }
__device__ __forceinline__ float cvtE(float v)         { return v; }

__device__ __forceinline__ unsigned long long dup2(float w) {
    unsigned long long r;
    asm("mov.b64 %0, {%1, %1};" : "=l"(r) : "f"(w));
    return r;
}
__device__ __forceinline__ void ffma2(unsigned long long& d,
                                      unsigned long long a,
                                      unsigned long long b) {
    asm("fma.rn.f32x2 %0, %1, %2, %0;" : "+l"(d) : "l"(a), "l"(b));
}

__device__ __forceinline__ int comp(const int4& v, int j) {
    return j == 0 ? v.x : (j == 1 ? v.y : (j == 2 ? v.z : v.w));
}

// ---------------- U=4 pipelined path ----------------
// idx: depth-2 prefetch (named A/B shift regs). LUT gathers: issued one
// j-step ahead of use so each gather has ~40cyc of FFMA work in its shadow.
template <typename E>
__device__ __forceinline__ void row_pass4(
    const int* __restrict__ widx,
    const E* __restrict__ lut,
    const float* __restrict__ bias,
    float* __restrict__ out,
    int rs, int lane)
{
    constexpr int U = 4;
    const ulonglong2* __restrict__ xa = reinterpret_cast<const ulonglong2*>(g_xa);
    const ulonglong2* __restrict__ xb = reinterpret_cast<const ulonglong2*>(g_xb);

    const int4* wbase = reinterpret_cast<const int4*>(widx) + (size_t)rs * (IN_F / 4) + lane;
    const E*    lbase = lut + (size_t)rs * (NGROW * 16);

    unsigned long long acc[U][4];
#pragma unroll
    for (int u = 0; u < U; u++)
#pragma unroll
        for (int j = 0; j < 4; j++) acc[u][j] = 0ull;

    int4 A[U], B[U];
#pragma unroll
    for (int u = 0; u < U; u++) {
        A[u] = __ldcg(wbase + u * (IN_F / 4));            // group 0
        B[u] = __ldcg(wbase + u * (IN_F / 4) + 32);       // group 1
    }

    // pre-gather weights for (g=0, j=0)
    float wn[U];
#pragma unroll
    for (int u = 0; u < U; u++)
        wn[u] = cvtE(__ldg(lbase + (size_t)u * (NGROW * 16) + comp(A[u], 0)));

#pragma unroll 1
    for (int g = 0; g < NGROW; g++) {
        int4 C[U];
#pragma unroll
        for (int u = 0; u < U; u++) {
            C[u] = A[u];
            A[u] = B[u];
        }
        if (g + 2 < NGROW) {
#pragma unroll
            for (int u = 0; u < U; u++)
                B[u] = __ldcg(wbase + u * (IN_F / 4) + (g + 2) * 32);
        }

#pragma unroll
        for (int j = 0; j < 4; j++) {
            float wcur[U];
#pragma unroll
            for (int u = 0; u < U; u++) wcur[u] = wn[u];

            // issue gathers for the NEXT (g,j) step before this step's FFMAs
            if (j < 3) {
#pragma unroll
                for (int u = 0; u < U; u++)
                    wn[u] = cvtE(__ldg(lbase + (size_t)u * (NGROW * 16)
                                       + g * 16 + comp(C[u], j + 1)));
            } else {
                int gn = (g + 1 < NGROW) ? g + 1 : g;   // dummy-safe at tail
#pragma unroll
                for (int u = 0; u < U; u++)
                    wn[u] = cvtE(__ldg(lbase + (size_t)u * (NGROW * 16)
                                       + gn * 16 + comp(A[u], 0)));
            }

            int xoff = (g * 4 + j) * 32 + lane;
            ulonglong2 va = __ldg(&xa[xoff]);   // L1-resident, coalesced
            ulonglong2 vb = __ldg(&xb[xoff]);
#pragma unroll
            for (int u = 0; u < U; u++) {
                unsigned long long w2 = dup2(wcur[u]);
                ffma2(acc[u][0], w2, va.x);
                ffma2(acc[u][1], w2, va.y);
                ffma2(acc[u][2], w2, vb.x);
                ffma2(acc[u][3], w2, vb.y);
            }
        }
    }

    // unpack and warp-reduce
    float accf[U][8];
#pragma unroll
    for (int u = 0; u < U; u++)
#pragma unroll
        for (int j = 0; j < 4; j++) {
            unsigned int lo, hi;
            asm("mov.b64 {%0, %1}, %2;" : "=r"(lo), "=r"(hi) : "l"(acc[u][j]));
            accf[u][2 * j]     = __uint_as_float(lo);
            accf[u][2 * j + 1] = __uint_as_float(hi);
        }

#pragma unroll
    for (int off = 16; off > 0; off >>= 1)
#pragma unroll
        for (int u = 0; u < U; u++)
#pragma unroll
            for (int b = 0; b < 8; b++)
                accf[u][b] += __shfl_xor_sync(0xffffffffu, accf[u][b], off);

    if (lane == 0) {
#pragma unroll
        for (int u = 0; u < U; u++) {
            float bv = bias[rs + u];
#pragma unroll
            for (int b = 0; b < 8; b++)
                out[(size_t)b * OUT_F + rs + u] = accf[u][b] + bv;
        }
    }
}

// ---------------- generic (tail) path: depth-1, no gather pipeline ----------------
template <int U, typename E>
__device__ __forceinline__ void row_pass(
    const int* __restrict__ widx,
    const E* __restrict__ lut,
    const float* __restrict__ bias,
    float* __restrict__ out,
    int rs, int lane)
{
    const ulonglong2* __restrict__ xa = reinterpret_cast<const ulonglong2*>(g_xa);
    const ulonglong2* __restrict__ xb = reinterpret_cast<const ulonglong2*>(g_xb);

    const int4* wbase = reinterpret_cast<const int4*>(widx) + (size_t)rs * (IN_F / 4) + lane;
    const E*    lbase = lut + (size_t)rs * (NGROW * 16);

    unsigned long long acc[U][4];
#pragma unroll
    for (int u = 0; u < U; u++)
#pragma unroll
        for (int j = 0; j < 4; j++) acc[u][j] = 0ull;

    int4 nxt[U];
#pragma unroll
    for (int u = 0; u < U; u++)
        nxt[u] = __ldcg(wbase + u * (IN_F / 4));

#pragma unroll 1
    for (int g = 0; g < NGROW; g++) {
        int4 cur[U];
#pragma unroll
        for (int u = 0; u < U; u++) cur[u] = nxt[u];
        if (g + 1 < NGROW) {
#pragma unroll
            for (int u = 0; u < U; u++)
                nxt[u] = __ldcg(wbase + u * (IN_F / 4) + (g + 1) * 32);
        }

#pragma unroll
        for (int j = 0; j < 4; j++) {
            int xoff = (g * 4 + j) * 32 + lane;
            ulonglong2 va = __ldg(&xa[xoff]);
            ulonglong2 vb = __ldg(&xb[xoff]);
#pragma unroll
            for (int u = 0; u < U; u++) {
                int id = comp(cur[u], j);
                float w = cvtE(__ldg(lbase + (size_t)u * (NGROW * 16) + g * 16 + id));
                unsigned long long w2 = dup2(w);
                ffma2(acc[u][0], w2, va.x);
                ffma2(acc[u][1], w2, va.y);
                ffma2(acc[u][2], w2, vb.x);
                ffma2(acc[u][3], w2, vb.y);
            }
        }
    }

    float accf[U][8];
#pragma unroll
    for (int u = 0; u < U; u++)
#pragma unroll
        for (int j = 0; j < 4; j++) {
            unsigned int lo, hi;
            asm("mov.b64 {%0, %1}, %2;" : "=r"(lo), "=r"(hi) : "l"(acc[u][j]));
            accf[u][2 * j]     = __uint_as_float(lo);
            accf[u][2 * j + 1] = __uint_as_float(hi);
        }

#pragma unroll
    for (int off = 16; off > 0; off >>= 1)
#pragma unroll
        for (int u = 0; u < U; u++)
#pragma unroll
            for (int b = 0; b < 8; b++)
                accf[u][b] += __shfl_xor_sync(0xffffffffu, accf[u][b], off);

    if (lane == 0) {
#pragma unroll
        for (int u = 0; u < U; u++) {
            float bv = bias[rs + u];
#pragma unroll
            for (int b = 0; b < 8; b++)
                out[(size_t)b * OUT_F + rs + u] = accf[u][b] + bv;
        }
    }
}

template <typename E>
__device__ __forceinline__ void dispatch_rows(
    const int* __restrict__ widx, const E* __restrict__ lut,
    const float* __restrict__ bias, float* __restrict__ out,
    int rs, int nr, int lane)
{
    if (nr == 4)      row_pass4<E>(widx, lut, bias, out, rs, lane);
    else if (nr == 5) { row_pass4<E>(widx, lut, bias, out, rs, lane);
                        row_pass<1, E>(widx, lut, bias, out, rs + 4, lane); }
    else if (nr == 3) row_pass<3, E>(widx, lut, bias, out, rs, lane);
    else if (nr == 2) row_pass<2, E>(widx, lut, bias, out, rs, lane);
    else if (nr == 1) row_pass<1, E>(widx, lut, bias, out, rs, lane);
    else {
        int r = rs;
        for (; r + 4 <= rs + nr; r += 4) row_pass4<E>(widx, lut, bias, out, r, lane);
        for (; r < rs + nr; r++)         row_pass<1, E>(widx, lut, bias, out, r, lane);
    }
}

__global__ void __launch_bounds__(TPB, 1) pallet_kernel(
    const int* __restrict__ widx,
    const void* __restrict__ lut,
    const float* __restrict__ bias,
    float* __restrict__ out,
    int nwarps)
{
    __shared__ int s_mode;
    int tid = threadIdx.x, warp = tid >> 5, lane = tid & 31;

    // inline dtype probe (warp 0): how was the fp16 LUT materialized?
    if (warp == 0) {
        const unsigned short* s = (const unsigned short*)lut;
        const float* f = (const float*)lut;
        int ch = 0, cb = 0, cf = 0;
        for (int t = lane; t < 64; t += 32) {
            unsigned short v = s[t];
            if (plaus(__half2float(__ushort_as_half(v)))) ch++;
            if (plaus(__uint_as_float(((unsigned)v) << 16))) cb++;   // bf16 -> f32
            if (plaus(f[t])) cf++;
        }
#pragma unroll
        for (int o = 16; o > 0; o >>= 1) {
            ch += __shfl_xor_sync(0xffffffffu, ch, o);
            cb += __shfl_xor_sync(0xffffffffu, cb, o);
            cf += __shfl_xor_sync(0xffffffffu, cf, o);
        }
        if (lane == 0) {
            int m = 0, best = ch;
            if (cb > best) { best = cb; m = 1; }
            if (cf > best) { best = cf; m = 2; }
            s_mode = m;
        }
    }
    __syncthreads();
    int mode = s_mode;

    int w = blockIdx.x * WPB + warp;
    long long s = ((long long)w * OUT_F) / nwarps;
    long long e = ((long long)(w + 1) * OUT_F) / nwarps;
    int rs = (int)s;
    int nr = (int)(e - s);

    if (mode == 0)
        dispatch_rows<__half>(widx, (const __half*)lut, bias, out, rs, nr, lane);
    else if (mode == 1)
        dispatch_rows<__nv_bfloat16>(widx, (const __nv_bfloat16*)lut, bias, out, rs, nr, lane);
    else
        dispatch_rows<float>(widx, (const float*)lut, bias, out, rs, nr, lane);
}

extern "C" void kernel_launch(void* const* d_in, const int* in_sizes, int n_in,
                              void* d_out, int out_size) {
    // Bind inputs by element count (all four distinct):
    //   x: 32768, weight_indices: 45088768, lut: 5636096, bias: 11008
    const float* x    = nullptr;
    const int*   widx = nullptr;
    const void*  lut  = nullptr;
    const float* bias = nullptr;

    for (int i = 0; i < n_in; i++) {
        long long n = in_sizes[i];
        if (n == 8LL * IN_F)                   x    = (const float*)d_in[i];
        else if (n == (long long)OUT_F * IN_F) widx = (const int*)d_in[i];
        else if (n == (long long)LUT_N)        lut  = d_in[i];
        else if (n == OUT_F)                   bias = (const float*)d_in[i];
    }
    if (!x || !widx || !lut || !bias) {
        x    = (const float*)d_in[0];
        widx = (const int*)d_in[1];
        lut  = d_in[2];
        bias = (const float*)d_in[3];
    }

    float* out = (float*)d_out;

    int dev = 0, sms = 148;
    cudaGetDevice(&dev);
    cudaDeviceGetAttribute(&sms, cudaDevAttrMultiProcessorCount, dev);

    transpose_x_kernel<<<(IN_F + 255) / 256, 256>>>(x);
    pallet_kernel<<<sms, TPB>>>(widx, lut, bias, out, sms * WPB);
}

// round 10
// speedup vs baseline: 1.3684x; 1.3684x over previous
#include <cuda_runtime.h>
#include <cuda_fp16.h>
#include <cuda_bf16.h>
#include <cstdint>

#define OUT_F 11008
#define IN_F  4096
#define NGROW 32            // groups per output row (4096/128)
#define LUT_N (352256 * 16)
#define TPB   512
#define WPB   16            // warps per block
#define STAGES 4
#define UMAX  5

#define STAGE_BYTES (UMAX * 512)                     // 2560 per stage per warp
#define WARP_BYTES  (STAGES * STAGE_BYTES)           // 10240
#define SMEM_TOTAL  (WPB * WARP_BYTES)               // 163840

// Permuted transposed x: slot = (g*4 + j)*32 + lane holds column c = g*128 + 4*lane + j
__device__ float4 g_xa[IN_F];   // batches 0-3
__device__ float4 g_xb[IN_F];   // batches 4-7

__global__ void transpose_x_kernel(const float* __restrict__ x) {
    int c = blockIdx.x * blockDim.x + threadIdx.x;
    if (c < IN_F) {
        int g = c >> 7, w = c & 127, l = w >> 2, j = w & 3;
        int slot = (g * 4 + j) * 32 + l;
        float4 a, b;
        a.x = x[0 * IN_F + c]; a.y = x[1 * IN_F + c];
        a.z = x[2 * IN_F + c]; a.w = x[3 * IN_F + c];
        b.x = x[4 * IN_F + c]; b.y = x[5 * IN_F + c];
        b.z = x[6 * IN_F + c]; b.w = x[7 * IN_F + c];
        g_xa[slot] = a; g_xb[slot] = b;
    }
}

__device__ __forceinline__ bool plaus(float v) {
    float a = fabsf(v);
    return isfinite(v) && a > 1e-4f && a < 0.25f;
}

__device__ __forceinline__ float cvtE(__half v)        { return __half2float(v); }
__device__ __forceinline__ float cvtE(__nv_bfloat16 v) { return __bfloat162float(v); }
__device__ __forceinline__ float cvtE(float v)         { return v; }

__device__ __forceinline__ unsigned long long dup2(float w) {
    unsigned long long r;
    asm("mov.b64 %0, {%1, %1};" : "=l"(r) : "f"(w));
    return r;
}
__device__ __forceinline__ void ffma2(unsigned long long& d,
                                      unsigned long long a,
                                      unsigned long long b) {
    asm("fma.rn.f32x2 %0, %1, %2, %0;" : "+l"(d) : "l"(a), "l"(b));
}

__device__ __forceinline__ void cpa16(uint32_t dst, const void* src) {
    asm volatile("cp.async.cg.shared.global [%0], [%1], 16;" :: "r"(dst), "l"(src));
}
__device__ __forceinline__ void cpa_commit() {
    asm volatile("cp.async.commit_group;");
}
template <int N>
__device__ __forceinline__ void cpa_wait() {
    asm volatile("cp.async.wait_group %0;" :: "n"(N));
}

// One group-step. St = compile-time ring stage (g % 4).
// wait<2> leaves groups g+1, g+2 in flight; we then issue g+3.
// Steady-state in-flight ~2.5 groups = ~6.4KB/warp of idx stream.
template <int St, int U, typename E>
__device__ __forceinline__ void group_step(
    int g,
    uint32_t warp_smem,                 // smem base (u32 addr) for this warp
    const char* smem_rd,                // generic-space base for LDS readback
    const int4* __restrict__ wbase,     // idx base (int4, +lane already applied for src math below)
    const E* __restrict__ lbase,
    const ulonglong2* __restrict__ xa,
    const ulonglong2* __restrict__ xb,
    unsigned long long (&acc)[U][4],
    int lane)
{
    cpa_wait<2>();   // stage St (group g) is now resident

    int4 cur[U];
#pragma unroll
    for (int u = 0; u < U; u++)
        cur[u] = *reinterpret_cast<const int4*>(
            smem_rd + St * STAGE_BYTES + u * 512 + lane * 16);

    // refill: group g+3 into stage (St+3)%4; always commit to keep counts uniform
    {
        constexpr int St3 = (St + 3) % STAGES;
        int gn = g + 3;
        if (gn < NGROW) {
#pragma unroll
            for (int u = 0; u < U; u++)
                cpa16(warp_smem + St3 * STAGE_BYTES + u * 512 + lane * 16,
                      wbase + u * (IN_F / 4) + gn * 32);
        }
        cpa_commit();
    }

#pragma unroll
    for (int j = 0; j < 4; j++) {
        int xoff = (g * 4 + j) * 32 + lane;
        ulonglong2 va = __ldg(&xa[xoff]);   // L1-resident, coalesced
        ulonglong2 vb = __ldg(&xb[xoff]);
#pragma unroll
        for (int u = 0; u < U; u++) {
            int id = reinterpret_cast<const int*>(&cur[u])[j];
            float w = cvtE(__ldg(lbase + (size_t)u * (NGROW * 16) + g * 16 + id));
            unsigned long long w2 = dup2(w);
            ffma2(acc[u][0], w2, va.x);
            ffma2(acc[u][1], w2, va.y);
            ffma2(acc[u][2], w2, vb.x);
            ffma2(acc[u][3], w2, vb.y);
        }
    }
}

template <int U, typename E>
__device__ __forceinline__ void row_pass(
    uint32_t warp_smem, const char* smem_rd,
    const int* __restrict__ widx,
    const E* __restrict__ lut,
    const float* __restrict__ bias,
    float* __restrict__ out,
    int rs, int lane)
{
    const ulonglong2* __restrict__ xa = reinterpret_cast<const ulonglong2*>(g_xa);
    const ulonglong2* __restrict__ xb = reinterpret_cast<const ulonglong2*>(g_xb);

    const int4* wbase = reinterpret_cast<const int4*>(widx) + (size_t)rs * (IN_F / 4) + lane;
    const E*    lbase = lut + (size_t)rs * (NGROW * 16);

    unsigned long long acc[U][4];
#pragma unroll
    for (int u = 0; u < U; u++)
#pragma unroll
        for (int j = 0; j < 4; j++) acc[u][j] = 0ull;

    // prologue: fill stages 0,1,2 with groups 0,1,2 (one commit each)
#pragma unroll
    for (int g = 0; g < 3; g++) {
#pragma unroll
        for (int u = 0; u < U; u++)
            cpa16(warp_smem + g * STAGE_BYTES + u * 512 + lane * 16,
                  wbase + u * (IN_F / 4) + g * 32);
        cpa_commit();
    }

#pragma unroll 1
    for (int g = 0; g < NGROW; g += 4) {
        group_step<0, U, E>(g,     warp_smem, smem_rd, wbase, lbase, xa, xb, acc, lane);
        group_step<1, U, E>(g + 1, warp_smem, smem_rd, wbase, lbase, xa, xb, acc, lane);
        group_step<2, U, E>(g + 2, warp_smem, smem_rd, wbase, lbase, xa, xb, acc, lane);
        group_step<3, U, E>(g + 3, warp_smem, smem_rd, wbase, lbase, xa, xb, acc, lane);
    }
    cpa_wait<0>();   // drain (tail commits were empty)

    // unpack and warp-reduce
    float accf[U][8];
#pragma unroll
    for (int u = 0; u < U; u++)
#pragma unroll
        for (int j = 0; j < 4; j++) {
            unsigned int lo, hi;
            asm("mov.b64 {%0, %1}, %2;" : "=r"(lo), "=r"(hi) : "l"(acc[u][j]));
            accf[u][2 * j]     = __uint_as_float(lo);
            accf[u][2 * j + 1] = __uint_as_float(hi);
        }

#pragma unroll
    for (int off = 16; off > 0; off >>= 1)
#pragma unroll
        for (int u = 0; u < U; u++)
#pragma unroll
            for (int b = 0; b < 8; b++)
                accf[u][b] += __shfl_xor_sync(0xffffffffu, accf[u][b], off);

    if (lane == 0) {
#pragma unroll
        for (int u = 0; u < U; u++) {
            float bv = bias[rs + u];
#pragma unroll
            for (int b = 0; b < 8; b++)
                out[(size_t)b * OUT_F + rs + u] = accf[u][b] + bv;
        }
    }
}

template <typename E>
__device__ __forceinline__ void dispatch_rows(
    uint32_t warp_smem, const char* smem_rd,
    const int* __restrict__ widx, const E* __restrict__ lut,
    const float* __restrict__ bias, float* __restrict__ out,
    int rs, int nr, int lane)
{
    switch (nr) {
        case 4: row_pass<4, E>(warp_smem, smem_rd, widx, lut, bias, out, rs, lane); break;
        case 5: row_pass<5, E>(warp_smem, smem_rd, widx, lut, bias, out, rs, lane); break;
        case 3: row_pass<3, E>(warp_smem, smem_rd, widx, lut, bias, out, rs, lane); break;
        case 2: row_pass<2, E>(warp_smem, smem_rd, widx, lut, bias, out, rs, lane); break;
        case 1: row_pass<1, E>(warp_smem, smem_rd, widx, lut, bias, out, rs, lane); break;
        default: {
            int r = rs;
            for (; r + 4 <= rs + nr; r += 4)
                row_pass<4, E>(warp_smem, smem_rd, widx, lut, bias, out, r, lane);
            for (; r < rs + nr; r++)
                row_pass<1, E>(warp_smem, smem_rd, widx, lut, bias, out, r, lane);
            break;
        }
    }
}

__global__ void __launch_bounds__(TPB, 1) pallet_kernel(
    const int* __restrict__ widx,
    const void* __restrict__ lut,
    const float* __restrict__ bias,
    float* __restrict__ out,
    int nwarps)
{
    extern __shared__ char smem[];
    __shared__ int s_mode;

    int tid = threadIdx.x, warp = tid >> 5, lane = tid & 31;

    // inline dtype probe (warp 0): how was the fp16 LUT materialized?
    if (warp == 0) {
        const unsigned short* s = (const unsigned short*)lut;
        const float* f = (const float*)lut;
        int ch = 0, cb = 0, cf = 0;
        for (int t = lane; t < 64; t += 32) {
            unsigned short v = s[t];
            if (plaus(__half2float(__ushort_as_half(v)))) ch++;
            if (plaus(__uint_as_float(((unsigned)v) << 16))) cb++;   // bf16 -> f32
            if (plaus(f[t])) cf++;
        }
#pragma unroll
        for (int o = 16; o > 0; o >>= 1) {
            ch += __shfl_xor_sync(0xffffffffu, ch, o);
            cb += __shfl_xor_sync(0xffffffffu, cb, o);
            cf += __shfl_xor_sync(0xffffffffu, cf, o);
        }
        if (lane == 0) {
            int m = 0, best = ch;
            if (cb > best) { best = cb; m = 1; }
            if (cf > best) { best = cf; m = 2; }
            s_mode = m;
        }
    }
    __syncthreads();
    int mode = s_mode;

    uint32_t smem_base = (uint32_t)__cvta_generic_to_shared(smem);
    uint32_t warp_smem = smem_base + warp * WARP_BYTES;
    const char* smem_rd = smem + warp * WARP_BYTES;

    int w = blockIdx.x * WPB + warp;
    long long s = ((long long)w * OUT_F) / nwarps;
    long long e = ((long long)(w + 1) * OUT_F) / nwarps;
    int rs = (int)s;
    int nr = (int)(e - s);

    if (mode == 0)
        dispatch_rows<__half>(warp_smem, smem_rd, widx, (const __half*)lut, bias, out, rs, nr, lane);
    else if (mode == 1)
        dispatch_rows<__nv_bfloat16>(warp_smem, smem_rd, widx, (const __nv_bfloat16*)lut, bias, out, rs, nr, lane);
    else
        dispatch_rows<float>(warp_smem, smem_rd, widx, (const float*)lut, bias, out, rs, nr, lane);
}

extern "C" void kernel_launch(void* const* d_in, const int* in_sizes, int n_in,
                              void* d_out, int out_size) {
    // Bind inputs by element count (all four distinct):
    //   x: 32768, weight_indices: 45088768, lut: 5636096, bias: 11008
    const float* x    = nullptr;
    const int*   widx = nullptr;
    const void*  lut  = nullptr;
    const float* bias = nullptr;

    for (int i = 0; i < n_in; i++) {
        long long n = in_sizes[i];
        if (n == 8LL * IN_F)                   x    = (const float*)d_in[i];
        else if (n == (long long)OUT_F * IN_F) widx = (const int*)d_in[i];
        else if (n == (long long)LUT_N)        lut  = d_in[i];
        else if (n == OUT_F)                   bias = (const float*)d_in[i];
    }
    if (!x || !widx || !lut || !bias) {
        x    = (const float*)d_in[0];
        widx = (const int*)d_in[1];
        lut  = d_in[2];
        bias = (const float*)d_in[3];
    }

    float* out = (float*)d_out;

    int dev = 0, sms = 148;
    cudaGetDevice(&dev);
    cudaDeviceGetAttribute(&sms, cudaDevAttrMultiProcessorCount, dev);

    cudaFuncSetAttribute(pallet_kernel,
                         cudaFuncAttributeMaxDynamicSharedMemorySize, SMEM_TOTAL);

    transpose_x_kernel<<<(IN_F + 255) / 256, 256>>>(x);
    pallet_kernel<<<sms, TPB, SMEM_TOTAL>>>(widx, lut, bias, out, sms * WPB);
}

// round 11
// speedup vs baseline: 1.5321x; 1.1197x over previous
#include <cuda_runtime.h>
#include <cuda_fp16.h>
#include <cuda_bf16.h>
#include <cstdint>

#define OUT_F 11008
#define IN_F  4096
#define NGROW 32            // groups per output row (4096/128)
#define LUT_N (352256 * 16)
#define TPB   512
#define WPB   16            // warps per block

// dynamic smem: s_xa[IN_F] (batches 0-3), s_xb[IN_F] (batches 4-7), each float4
#define SMEM_TOTAL (2 * IN_F * 16)   // 131072

__device__ __forceinline__ bool plaus(float v) {
    float a = fabsf(v);
    return isfinite(v) && a > 1e-4f && a < 0.25f;
}

__device__ __forceinline__ float cvtE(__half v)        { return __half2float(v); }
__device__ __forceinline__ float cvtE(__nv_bfloat16 v) { return __bfloat162float(v); }
__device__ __forceinline__ float cvtE(float v)         { return v; }

__device__ __forceinline__ unsigned long long dup2(float w) {
    unsigned long long r;
    asm("mov.b64 %0, {%1, %1};" : "=l"(r) : "f"(w));
    return r;
}
__device__ __forceinline__ void ffma2(unsigned long long& d,
                                      unsigned long long a,
                                      unsigned long long b) {
    asm("fma.rn.f32x2 %0, %1, %2, %0;" : "+l"(d) : "l"(a), "l"(b));
}

// x tiles come from SHARED memory (crossbar port), not L1tex.
// Layout: slot = (g*4 + j)*32 + lane holds column c = g*128 + 4*lane + j.
template <int U, typename E>
__device__ __forceinline__ void row_pass(
    const ulonglong2* __restrict__ sxa,
    const ulonglong2* __restrict__ sxb,
    const int* __restrict__ widx,
    const E* __restrict__ lut,
    const float* __restrict__ bias,
    float* __restrict__ out,
    int rs, int lane)
{
    const int4* wbase = reinterpret_cast<const int4*>(widx) + (size_t)rs * (IN_F / 4) + lane;
    const E*    lbase = lut + (size_t)rs * (NGROW * 16);

    unsigned long long acc[U][4];
#pragma unroll
    for (int u = 0; u < U; u++)
#pragma unroll
        for (int j = 0; j < 4; j++) acc[u][j] = 0ull;

    int4 nxt[U];
#pragma unroll
    for (int u = 0; u < U; u++)
        nxt[u] = __ldcg(wbase + u * (IN_F / 4));

#pragma unroll 1
    for (int g = 0; g < NGROW; g++) {
        int4 cur[U];
#pragma unroll
        for (int u = 0; u < U; u++) cur[u] = nxt[u];

        if (g + 1 < NGROW) {
#pragma unroll
            for (int u = 0; u < U; u++)
                nxt[u] = __ldcg(wbase + u * (IN_F / 4) + (g + 1) * 32);
        }

#pragma unroll
        for (int j = 0; j < 4; j++) {
            int xoff = (g * 4 + j) * 32 + lane;
            ulonglong2 va = sxa[xoff];   // LDS.128, conflict-free
            ulonglong2 vb = sxb[xoff];
#pragma unroll
            for (int u = 0; u < U; u++) {
                int id = reinterpret_cast<const int*>(&cur[u])[j];
                float w = cvtE(__ldg(lbase + (size_t)u * (NGROW * 16) + g * 16 + id));
                unsigned long long w2 = dup2(w);
                ffma2(acc[u][0], w2, va.x);
                ffma2(acc[u][1], w2, va.y);
                ffma2(acc[u][2], w2, vb.x);
                ffma2(acc[u][3], w2, vb.y);
            }
        }
    }

    // unpack and warp-reduce
    float accf[U][8];
#pragma unroll
    for (int u = 0; u < U; u++)
#pragma unroll
        for (int j = 0; j < 4; j++) {
            unsigned int lo, hi;
            asm("mov.b64 {%0, %1}, %2;" : "=r"(lo), "=r"(hi) : "l"(acc[u][j]));
            accf[u][2 * j]     = __uint_as_float(lo);
            accf[u][2 * j + 1] = __uint_as_float(hi);
        }

#pragma unroll
    for (int off = 16; off > 0; off >>= 1)
#pragma unroll
        for (int u = 0; u < U; u++)
#pragma unroll
            for (int b = 0; b < 8; b++)
                accf[u][b] += __shfl_xor_sync(0xffffffffu, accf[u][b], off);

    if (lane == 0) {
#pragma unroll
        for (int u = 0; u < U; u++) {
            float bv = bias[rs + u];
#pragma unroll
            for (int b = 0; b < 8; b++)
                out[(size_t)b * OUT_F + rs + u] = accf[u][b] + bv;
        }
    }
}

template <typename E>
__device__ __forceinline__ void dispatch_rows(
    const ulonglong2* __restrict__ sxa, const ulonglong2* __restrict__ sxb,
    const int* __restrict__ widx, const E* __restrict__ lut,
    const float* __restrict__ bias, float* __restrict__ out,
    int rs, int nr, int lane)
{
    switch (nr) {
        case 4: row_pass<4, E>(sxa, sxb, widx, lut, bias, out, rs, lane); break;
        case 5: row_pass<5, E>(sxa, sxb, widx, lut, bias, out, rs, lane); break;
        case 3: row_pass<3, E>(sxa, sxb, widx, lut, bias, out, rs, lane); break;
        case 2: row_pass<2, E>(sxa, sxb, widx, lut, bias, out, rs, lane); break;
        case 1: row_pass<1, E>(sxa, sxb, widx, lut, bias, out, rs, lane); break;
        default: {
            int r = rs;
            for (; r + 4 <= rs + nr; r += 4) row_pass<4, E>(sxa, sxb, widx, lut, bias, out, r, lane);
            for (; r < rs + nr; r++)         row_pass<1, E>(sxa, sxb, widx, lut, bias, out, r, lane);
            break;
        }
    }
}

__global__ void __launch_bounds__(TPB, 1) pallet_kernel(
    const float* __restrict__ x,
    const int* __restrict__ widx,
    const void* __restrict__ lut,
    const float* __restrict__ bias,
    float* __restrict__ out,
    int nwarps)
{
    extern __shared__ char smem[];
    ulonglong2* sxa = reinterpret_cast<ulonglong2*>(smem);
    ulonglong2* sxb = sxa + IN_F;
    __shared__ int s_mode;

    int tid = threadIdx.x, warp = tid >> 5, lane = tid & 31;

    // warp 0: dtype probe (how was the fp16 LUT materialized?)
    if (warp == 0) {
        const unsigned short* s = (const unsigned short*)lut;
        const float* f = (const float*)lut;
        int ch = 0, cb = 0, cf = 0;
        for (int t = lane; t < 64; t += 32) {
            unsigned short v = s[t];
            if (plaus(__half2float(__ushort_as_half(v)))) ch++;
            if (plaus(__uint_as_float(((unsigned)v) << 16))) cb++;   // bf16 -> f32
            if (plaus(f[t])) cf++;
        }
#pragma unroll
        for (int o = 16; o > 0; o >>= 1) {
            ch += __shfl_xor_sync(0xffffffffu, ch, o);
            cb += __shfl_xor_sync(0xffffffffu, cb, o);
            cf += __shfl_xor_sync(0xffffffffu, cf, o);
        }
        if (lane == 0) {
            int m = 0, best = ch;
            if (cb > best) { best = cb; m = 1; }
            if (cf > best) { best = cf; m = 2; }
            s_mode = m;
        }
    }

    // all threads: fill x into smem with the permuted transposed layout
    for (int c = tid; c < IN_F; c += TPB) {
        int g = c >> 7, w = c & 127, l = w >> 2, j = w & 3;
        int slot = (g * 4 + j) * 32 + l;
        float4 a, b;
        a.x = x[0 * IN_F + c]; a.y = x[1 * IN_F + c];
        a.z = x[2 * IN_F + c]; a.w = x[3 * IN_F + c];
        b.x = x[4 * IN_F + c]; b.y = x[5 * IN_F + c];
        b.z = x[6 * IN_F + c]; b.w = x[7 * IN_F + c];
        reinterpret_cast<float4*>(sxa)[slot] = a;
        reinterpret_cast<float4*>(sxb)[slot] = b;
    }
    __syncthreads();
    int mode = s_mode;

    int w = blockIdx.x * WPB + warp;
    long long s = ((long long)w * OUT_F) / nwarps;
    long long e = ((long long)(w + 1) * OUT_F) / nwarps;
    int rs = (int)s;
    int nr = (int)(e - s);

    if (mode == 0)
        dispatch_rows<__half>(sxa, sxb, widx, (const __half*)lut, bias, out, rs, nr, lane);
    else if (mode == 1)
        dispatch_rows<__nv_bfloat16>(sxa, sxb, widx, (const __nv_bfloat16*)lut, bias, out, rs, nr, lane);
    else
        dispatch_rows<float>(sxa, sxb, widx, (const float*)lut, bias, out, rs, nr, lane);
}

extern "C" void kernel_launch(void* const* d_in, const int* in_sizes, int n_in,
                              void* d_out, int out_size) {
    // Bind inputs by element count (all four distinct):
    //   x: 32768, weight_indices: 45088768, lut: 5636096, bias: 11008
    const float* x    = nullptr;
    const int*   widx = nullptr;
    const void*  lut  = nullptr;
    const float* bias = nullptr;

    for (int i = 0; i < n_in; i++) {
        long long n = in_sizes[i];
        if (n == 8LL * IN_F)                   x    = (const float*)d_in[i];
        else if (n == (long long)OUT_F * IN_F) widx = (const int*)d_in[i];
        else if (n == (long long)LUT_N)        lut  = d_in[i];
        else if (n == OUT_F)                   bias = (const float*)d_in[i];
    }
    if (!x || !widx || !lut || !bias) {
        x    = (const float*)d_in[0];
        widx = (const int*)d_in[1];
        lut  = d_in[2];
        bias = (const float*)d_in[3];
    }

    float* out = (float*)d_out;

    int dev = 0, sms = 148;
    cudaGetDevice(&dev);
    cudaDeviceGetAttribute(&sms, cudaDevAttrMultiProcessorCount, dev);

    cudaFuncSetAttribute(pallet_kernel,
                         cudaFuncAttributeMaxDynamicSharedMemorySize, SMEM_TOTAL);

    pallet_kernel<<<sms, TPB, SMEM_TOTAL>>>(x, widx, lut, bias, out, sms * WPB);
}

// round 12
// speedup vs baseline: 1.5403x; 1.0054x over previous
#include <cuda_runtime.h>
#include <cuda_fp16.h>
#include <cuda_bf16.h>
#include <cstdint>

#define OUT_F 11008
#define IN_F  4096
#define NGROW 32            // groups per output row (4096/128)
#define LUT_N (352256 * 16)
#define TPB   512
#define WPB   16            // warps per block

// Permuted transposed x: slot = (g*4 + j)*32 + lane holds column c = g*128 + 4*lane + j
__device__ float4 g_xa[IN_F];   // batches 0-3
__device__ float4 g_xb[IN_F];   // batches 4-7

__global__ void transpose_x_kernel(const float* __restrict__ x) {
    int c = blockIdx.x * blockDim.x + threadIdx.x;
    if (c < IN_F) {
        int g = c >> 7, w = c & 127, l = w >> 2, j = w & 3;
        int slot = (g * 4 + j) * 32 + l;
        float4 a, b;
        a.x = x[0 * IN_F + c]; a.y = x[1 * IN_F + c];
        a.z = x[2 * IN_F + c]; a.w = x[3 * IN_F + c];
        b.x = x[4 * IN_F + c]; b.y = x[5 * IN_F + c];
        b.z = x[6 * IN_F + c]; b.w = x[7 * IN_F + c];
        g_xa[slot] = a; g_xb[slot] = b;
    }
}

__device__ __forceinline__ bool plaus(float v) {
    float a = fabsf(v);
    return isfinite(v) && a > 1e-4f && a < 0.25f;
}

__device__ __forceinline__ float cvtE(__half v)        { return __half2float(v); }
__device__ __forceinline__ float cvtE(__nv_bfloat16 v) { return __bfloat162float(v); }
__device__ __forceinline__ float cvtE(float v)         { return v; }

__device__ __forceinline__ unsigned long long dup2(float w) {
    unsigned long long r;
    asm("mov.b64 %0, {%1, %1};" : "=l"(r) : "f"(w));
    return r;
}
__device__ __forceinline__ void ffma2(unsigned long long& d,
                                      unsigned long long a,
                                      unsigned long long b) {
    asm("fma.rn.f32x2 %0, %1, %2, %0;" : "+l"(d) : "l"(a), "l"(b));
}
__device__ __forceinline__ void prefetchL1(const void* p) {
    asm volatile("prefetch.global.L1 [%0];" :: "l"(p));
}

// r4 champion structure + LUT row prefetch (no other changes)
template <int U, typename E>
__device__ __forceinline__ void row_pass(
    const int* __restrict__ widx,
    const E* __restrict__ lut,
    const float* __restrict__ bias,
    float* __restrict__ out,
    int rs, int lane)
{
    const ulonglong2* __restrict__ xa = reinterpret_cast<const ulonglong2*>(g_xa);
    const ulonglong2* __restrict__ xb = reinterpret_cast<const ulonglong2*>(g_xb);

    const int4* wbase = reinterpret_cast<const int4*>(widx) + (size_t)rs * (IN_F / 4) + lane;
    const E*    lbase = lut + (size_t)rs * (NGROW * 16);

    unsigned long long acc[U][4];
#pragma unroll
    for (int u = 0; u < U; u++)
#pragma unroll
        for (int j = 0; j < 4; j++) acc[u][j] = 0ull;

    int4 nxt[U];
#pragma unroll
    for (int u = 0; u < U; u++) {
        nxt[u] = __ldcg(wbase + u * (IN_F / 4));
        prefetchL1(lbase + (size_t)u * (NGROW * 16));   // warm group-0 LUT rows
    }

    for (int g = 0; g < NGROW; g++) {
        int4 cur[U];
#pragma unroll
        for (int u = 0; u < U; u++) cur[u] = nxt[u];

        if (g + 1 < NGROW) {
#pragma unroll
            for (int u = 0; u < U; u++) {
                nxt[u] = __ldcg(wbase + u * (IN_F / 4) + (g + 1) * 32);
                // warm next group's LUT rows: removes the first-touch miss
                // from the dependent gather->FFMA chain (zero register cost)
                prefetchL1(lbase + (size_t)u * (NGROW * 16) + (g + 1) * 16);
            }
        }

#pragma unroll
        for (int j = 0; j < 4; j++) {
            int xoff = (g * 4 + j) * 32 + lane;
            ulonglong2 va = __ldg(&xa[xoff]);   // L1-resident, coalesced
            ulonglong2 vb = __ldg(&xb[xoff]);
#pragma unroll
            for (int u = 0; u < U; u++) {
                int id = reinterpret_cast<const int*>(&cur[u])[j];
                float w = cvtE(__ldg(lbase + (size_t)u * (NGROW * 16) + g * 16 + id));
                unsigned long long w2 = dup2(w);
                ffma2(acc[u][0], w2, va.x);
                ffma2(acc[u][1], w2, va.y);
                ffma2(acc[u][2], w2, vb.x);
                ffma2(acc[u][3], w2, vb.y);
            }
        }
    }

    // unpack and warp-reduce
    float accf[U][8];
#pragma unroll
    for (int u = 0; u < U; u++)
#pragma unroll
        for (int j = 0; j < 4; j++) {
            unsigned int lo, hi;
            asm("mov.b64 {%0, %1}, %2;" : "=r"(lo), "=r"(hi) : "l"(acc[u][j]));
            accf[u][2 * j]     = __uint_as_float(lo);
            accf[u][2 * j + 1] = __uint_as_float(hi);
        }

#pragma unroll
    for (int off = 16; off > 0; off >>= 1)
#pragma unroll
        for (int u = 0; u < U; u++)
#pragma unroll
            for (int b = 0; b < 8; b++)
                accf[u][b] += __shfl_xor_sync(0xffffffffu, accf[u][b], off);

    if (lane == 0) {
#pragma unroll
        for (int u = 0; u < U; u++) {
            float bv = bias[rs + u];
#pragma unroll
            for (int b = 0; b < 8; b++)
                out[(size_t)b * OUT_F + rs + u] = accf[u][b] + bv;
        }
    }
}

template <typename E>
__device__ __forceinline__ void dispatch_rows(
    const int* __restrict__ widx, const E* __restrict__ lut,
    const float* __restrict__ bias, float* __restrict__ out,
    int rs, int nr, int lane)
{
    switch (nr) {
        case 4: row_pass<4, E>(widx, lut, bias, out, rs, lane); break;
        case 5: row_pass<5, E>(widx, lut, bias, out, rs, lane); break;
        case 3: row_pass<3, E>(widx, lut, bias, out, rs, lane); break;
        case 2: row_pass<2, E>(widx, lut, bias, out, rs, lane); break;
        case 1: row_pass<1, E>(widx, lut, bias, out, rs, lane); break;
        default: {
            int r = rs;
            for (; r + 4 <= rs + nr; r += 4) row_pass<4, E>(widx, lut, bias, out, r, lane);
            for (; r < rs + nr; r++)         row_pass<1, E>(widx, lut, bias, out, r, lane);
            break;
        }
    }
}

__global__ void __launch_bounds__(TPB, 1) pallet_kernel(
    const int* __restrict__ widx,
    const void* __restrict__ lut,
    const float* __restrict__ bias,
    float* __restrict__ out,
    int nwarps)
{
    __shared__ int s_mode;
    int tid = threadIdx.x, warp = tid >> 5, lane = tid & 31;

    // inline dtype probe (warp 0): how was the fp16 LUT materialized?
    if (warp == 0) {
        const unsigned short* s = (const unsigned short*)lut;
        const float* f = (const float*)lut;
        int ch = 0, cb = 0, cf = 0;
        for (int t = lane; t < 64; t += 32) {
            unsigned short v = s[t];
            if (plaus(__half2float(__ushort_as_half(v)))) ch++;
            if (plaus(__uint_as_float(((unsigned)v) << 16))) cb++;   // bf16 -> f32
            if (plaus(f[t])) cf++;
        }
#pragma unroll
        for (int o = 16; o > 0; o >>= 1) {
            ch += __shfl_xor_sync(0xffffffffu, ch, o);
            cb += __shfl_xor_sync(0xffffffffu, cb, o);
            cf += __shfl_xor_sync(0xffffffffu, cf, o);
        }
        if (lane == 0) {
            int m = 0, best = ch;
            if (cb > best) { best = cb; m = 1; }
            if (cf > best) { best = cf; m = 2; }
            s_mode = m;
        }
    }
    __syncthreads();
    int mode = s_mode;

    int w = blockIdx.x * WPB + warp;
    long long s = ((long long)w * OUT_F) / nwarps;
    long long e = ((long long)(w + 1) * OUT_F) / nwarps;
    int rs = (int)s;
    int nr = (int)(e - s);

    if (mode == 0)
        dispatch_rows<__half>(widx, (const __half*)lut, bias, out, rs, nr, lane);
    else if (mode == 1)
        dispatch_rows<__nv_bfloat16>(widx, (const __nv_bfloat16*)lut, bias, out, rs, nr, lane);
    else
        dispatch_rows<float>(widx, (const float*)lut, bias, out, rs, nr, lane);
}

extern "C" void kernel_launch(void* const* d_in, const int* in_sizes, int n_in,
                              void* d_out, int out_size) {
    // Bind inputs by element count (all four distinct):
    //   x: 32768, weight_indices: 45088768, lut: 5636096, bias: 11008
    const float* x    = nullptr;
    const int*   widx = nullptr;
    const void*  lut  = nullptr;
    const float* bias = nullptr;

    for (int i = 0; i < n_in; i++) {
        long long n = in_sizes[i];
        if (n == 8LL * IN_F)                   x    = (const float*)d_in[i];
        else if (n == (long long)OUT_F * IN_F) widx = (const int*)d_in[i];
        else if (n == (long long)LUT_N)        lut  = d_in[i];
        else if (n == OUT_F)                   bias = (const float*)d_in[i];
    }
    if (!x || !widx || !lut || !bias) {
        x    = (const float*)d_in[0];
        widx = (const int*)d_in[1];
        lut  = d_in[2];
        bias = (const float*)d_in[3];
    }

    float* out = (float*)d_out;

    int dev = 0, sms = 148;
    cudaGetDevice(&dev);
    cudaDeviceGetAttribute(&sms, cudaDevAttrMultiProcessorCount, dev);

    transpose_x_kernel<<<(IN_F + 255) / 256, 256>>>(x);
    pallet_kernel<<<sms, TPB>>>(widx, lut, bias, out, sms * WPB);
}